// round 4
// baseline (speedup 1.0000x reference)
#include <cuda_runtime.h>

// LIF neuron scan, round 3: software-pipelined batched loads.
// x: [B=32, N=16384, T=100] float32 -> out spikes, same shape.
// decay = 0.5, V_TH = 0.5. One thread per neuron row (524288 rows).
//
// Row = 25 float4, split into 5 groups of 5. Double-buffered: loads for
// group g+1 are issued BEFORE the dependent LIF chain of group g runs, so
// memory latency overlaps compute. Sustained per-thread MLP ~= 5.

#define T_STEPS 100
#define N_VEC   (T_STEPS / 4)   // 25
#define GRP     5               // float4 per group
#define NGRP    (N_VEC / GRP)   // 5

__global__ __launch_bounds__(256) void lif_kernel(const float* __restrict__ x,
                                                  float* __restrict__ out,
                                                  int n_rows) {
    int row = blockIdx.x * blockDim.x + threadIdx.x;
    if (row >= n_rows) return;

    const float4* __restrict__ xr   = reinterpret_cast<const float4*>(x)   + (long long)row * N_VEC;
    float4* __restrict__       outr = reinterpret_cast<float4*>(out)       + (long long)row * N_VEC;

    const float decay = 0.5f;
    const float vth   = 0.5f;

    float v = 0.0f;

    // Prologue: load group 0.
    float4 cur[GRP];
    #pragma unroll
    for (int j = 0; j < GRP; ++j) cur[j] = __ldg(&xr[j]);

    #pragma unroll
    for (int g = 0; g < NGRP; ++g) {
        // Issue next group's loads before consuming the current group.
        float4 nxt[GRP];
        if (g + 1 < NGRP) {
            #pragma unroll
            for (int j = 0; j < GRP; ++j) nxt[j] = __ldg(&xr[(g + 1) * GRP + j]);
        }

        // Dependent LIF chain over the 20 timesteps of the current group.
        #pragma unroll
        for (int j = 0; j < GRP; ++j) {
            float4 xi = cur[j];
            float4 so;

            v = fmaf(v, decay, xi.x);
            so.x = (v > vth) ? 1.0f : 0.0f;
            v = fmaf(so.x, -vth, v);

            v = fmaf(v, decay, xi.y);
            so.y = (v > vth) ? 1.0f : 0.0f;
            v = fmaf(so.y, -vth, v);

            v = fmaf(v, decay, xi.z);
            so.z = (v > vth) ? 1.0f : 0.0f;
            v = fmaf(so.z, -vth, v);

            v = fmaf(v, decay, xi.w);
            so.w = (v > vth) ? 1.0f : 0.0f;
            v = fmaf(so.w, -vth, v);

            outr[g * GRP + j] = so;
        }

        #pragma unroll
        for (int j = 0; j < GRP; ++j) cur[j] = nxt[j];
    }
}

extern "C" void kernel_launch(void* const* d_in, const int* in_sizes, int n_in,
                              void* d_out, int out_size) {
    const float* x = (const float*)d_in[0];
    float* out = (float*)d_out;

    int n_rows = in_sizes[0] / T_STEPS;   // 524288

    int threads = 256;
    int blocks = (n_rows + threads - 1) / threads;
    lif_kernel<<<blocks, threads>>>(x, out, n_rows);
}

// round 5
// speedup vs baseline: 2.1220x; 2.1220x over previous
#include <cuda_runtime.h>

// LIF neuron scan, round 4: pipelined loads + register ceiling raised.
// KEY CHANGE vs round 3: __launch_bounds__(256, 2). Rounds 2/3 both compiled
// to regs=32 (ptxas full-occupancy heuristic), which forcibly re-serialized
// the load pipeline back to MLP~1 and produced identical 229us results.
// (256,2) raises the per-thread register cap to 128 so the 5-deep float4
// double buffer can actually live in registers.
//
// x: [B=32, N=16384, T=100] float32 -> out spikes, same shape.
// decay = 0.5, V_TH = 0.5. One thread per neuron row (524288 rows).

#define T_STEPS 100
#define N_VEC   (T_STEPS / 4)   // 25
#define GRP     5               // float4 per group
#define NGRP    (N_VEC / GRP)   // 5

__global__ __launch_bounds__(256, 2) void lif_kernel(const float* __restrict__ x,
                                                     float* __restrict__ out,
                                                     int n_rows) {
    int row = blockIdx.x * blockDim.x + threadIdx.x;
    if (row >= n_rows) return;

    const float4* __restrict__ xr   = reinterpret_cast<const float4*>(x)   + (long long)row * N_VEC;
    float4* __restrict__       outr = reinterpret_cast<float4*>(out)       + (long long)row * N_VEC;

    const float decay = 0.5f;
    const float vth   = 0.5f;

    float v = 0.0f;

    // Prologue: group 0 loads in flight.
    float4 cur[GRP];
    #pragma unroll
    for (int j = 0; j < GRP; ++j) cur[j] = __ldg(&xr[j]);

    #pragma unroll
    for (int g = 0; g < NGRP; ++g) {
        // Issue next group's 5 independent loads BEFORE consuming current group.
        float4 nxt[GRP];
        if (g + 1 < NGRP) {
            #pragma unroll
            for (int j = 0; j < GRP; ++j) nxt[j] = __ldg(&xr[(g + 1) * GRP + j]);
        }

        // Dependent LIF chain over the 20 timesteps of the current group.
        #pragma unroll
        for (int j = 0; j < GRP; ++j) {
            float4 xi = cur[j];
            float4 so;

            v = fmaf(v, decay, xi.x);
            so.x = (v > vth) ? 1.0f : 0.0f;
            v = fmaf(so.x, -vth, v);

            v = fmaf(v, decay, xi.y);
            so.y = (v > vth) ? 1.0f : 0.0f;
            v = fmaf(so.y, -vth, v);

            v = fmaf(v, decay, xi.z);
            so.z = (v > vth) ? 1.0f : 0.0f;
            v = fmaf(so.z, -vth, v);

            v = fmaf(v, decay, xi.w);
            so.w = (v > vth) ? 1.0f : 0.0f;
            v = fmaf(so.w, -vth, v);

            outr[g * GRP + j] = so;
        }

        #pragma unroll
        for (int j = 0; j < GRP; ++j) cur[j] = nxt[j];
    }
}

extern "C" void kernel_launch(void* const* d_in, const int* in_sizes, int n_in,
                              void* d_out, int out_size) {
    const float* x = (const float*)d_in[0];
    float* out = (float*)d_out;

    int n_rows = in_sizes[0] / T_STEPS;   // 524288

    int threads = 256;
    int blocks = (n_rows + threads - 1) / threads;
    lif_kernel<<<blocks, threads>>>(x, out, n_rows);
}

// round 6
// speedup vs baseline: 2.6089x; 1.2295x over previous
#include <cuda_runtime.h>

// LIF neuron scan, round 5: shared-memory staged, fully coalesced GMEM.
//
// Round-4 diagnosis: strided per-row access made every LDG.128/STG.128 a
// 32-wavefront L1tex instruction; total wavefronts ~26M / 148 SM ~= runtime.
// Fix: a block of 128 consecutive rows is a CONTIGUOUS 50 KB gmem region.
//   Phase L: coalesced gmem->smem copy (4 wf/instr, MLP=25 per thread)
//   Phase C: per-thread row scan from smem (LDS.128, conflict-free: bank
//            starts 4(r+i) mod 32 cover all 32 banks per 8-lane phase)
//   Phase S: coalesced smem->gmem store of the spike tile.
// smem = 2 x 50 KB = 100 KB/CTA -> 2 CTAs/SM.

#define T_STEPS   100
#define T_VEC     (T_STEPS / 4)        // 25 float4 per row
#define ROWS_CTA  128
#define TILE_V4   (ROWS_CTA * T_VEC)   // 3200 float4 = 50 KB

__global__ __launch_bounds__(ROWS_CTA, 2) void lif_kernel(const float4* __restrict__ x,
                                                          float4* __restrict__ out) {
    extern __shared__ float4 smem[];           // [2 * TILE_V4]
    float4* sin  = smem;
    float4* sout = smem + TILE_V4;

    const int tid = threadIdx.x;
    const long long base = (long long)blockIdx.x * TILE_V4;

    // ---- Phase L: coalesced gmem -> smem (25 independent LDG.128/thread) ----
    #pragma unroll
    for (int i = 0; i < T_VEC; ++i) {
        sin[tid + ROWS_CTA * i] = x[base + tid + ROWS_CTA * i];
    }
    __syncthreads();

    // ---- Phase C: serial LIF scan of this thread's row, smem -> smem ----
    const float decay = 0.5f;
    const float vth   = 0.5f;
    float v = 0.0f;

    const float4* __restrict__ rowi = sin  + tid * T_VEC;
    float4* __restrict__       rowo = sout + tid * T_VEC;

    #pragma unroll
    for (int i = 0; i < T_VEC; ++i) {
        float4 xi = rowi[i];
        float4 so;

        v = fmaf(v, decay, xi.x);
        so.x = (v > vth) ? 1.0f : 0.0f;
        v = fmaf(so.x, -vth, v);

        v = fmaf(v, decay, xi.y);
        so.y = (v > vth) ? 1.0f : 0.0f;
        v = fmaf(so.y, -vth, v);

        v = fmaf(v, decay, xi.z);
        so.z = (v > vth) ? 1.0f : 0.0f;
        v = fmaf(so.z, -vth, v);

        v = fmaf(v, decay, xi.w);
        so.w = (v > vth) ? 1.0f : 0.0f;
        v = fmaf(so.w, -vth, v);

        rowo[i] = so;
    }
    __syncthreads();

    // ---- Phase S: coalesced smem -> gmem store ----
    #pragma unroll
    for (int i = 0; i < T_VEC; ++i) {
        out[base + tid + ROWS_CTA * i] = sout[tid + ROWS_CTA * i];
    }
}

extern "C" void kernel_launch(void* const* d_in, const int* in_sizes, int n_in,
                              void* d_out, int out_size) {
    const float4* x = (const float4*)d_in[0];
    float4* out = (float4*)d_out;

    int n_rows = in_sizes[0] / T_STEPS;          // 524288
    int blocks = n_rows / ROWS_CTA;              // 4096

    size_t smem_bytes = 2 * TILE_V4 * sizeof(float4);   // 100 KB
    static bool attr_set = false;
    if (!attr_set) {
        cudaFuncSetAttribute(lif_kernel, cudaFuncAttributeMaxDynamicSharedMemorySize,
                             (int)smem_bytes);
        attr_set = true;
    }
    lif_kernel<<<blocks, ROWS_CTA, smem_bytes>>>(x, out);
}

// round 7
// speedup vs baseline: 2.7371x; 1.0491x over previous
#include <cuda_runtime.h>

// LIF neuron scan, round 6: in-place smem tile -> 4 CTAs/SM for phase overlap.
//
// Round-5 diagnosis: DRAM stuck at 54% because phases (load/compute/store)
// serialize and only 2 CTAs/SM were resident to cover each other's compute
// bubble. Fix: drop the separate output tile -- the spike overwrites its own
// input element in smem (per-thread read-then-write, no cross-thread hazard).
// smem: 100 KB -> 50 KB per CTA => 4 CTAs/SM, 16 warps, staggered phases.

#define T_STEPS   100
#define T_VEC     (T_STEPS / 4)        // 25 float4 per row
#define ROWS_CTA  128
#define TILE_V4   (ROWS_CTA * T_VEC)   // 3200 float4 = 50 KB

__global__ __launch_bounds__(ROWS_CTA, 4) void lif_kernel(const float4* __restrict__ x,
                                                          float4* __restrict__ out) {
    extern __shared__ float4 tile[];           // [TILE_V4], used in-place
    const int tid = threadIdx.x;
    const long long base = (long long)blockIdx.x * TILE_V4;

    // ---- Phase L: coalesced gmem -> smem (25 independent LDG.128/thread) ----
    #pragma unroll
    for (int i = 0; i < T_VEC; ++i) {
        tile[tid + ROWS_CTA * i] = x[base + tid + ROWS_CTA * i];
    }
    __syncthreads();

    // ---- Phase C: serial LIF scan of this thread's row, in-place in smem ----
    const float decay = 0.5f;
    const float vth   = 0.5f;
    float v = 0.0f;

    float4* __restrict__ row = tile + tid * T_VEC;

    #pragma unroll
    for (int i = 0; i < T_VEC; ++i) {
        float4 xi = row[i];
        float4 so;

        v = fmaf(v, decay, xi.x);
        so.x = (v > vth) ? 1.0f : 0.0f;
        v = fmaf(so.x, -vth, v);

        v = fmaf(v, decay, xi.y);
        so.y = (v > vth) ? 1.0f : 0.0f;
        v = fmaf(so.y, -vth, v);

        v = fmaf(v, decay, xi.z);
        so.z = (v > vth) ? 1.0f : 0.0f;
        v = fmaf(so.z, -vth, v);

        v = fmaf(v, decay, xi.w);
        so.w = (v > vth) ? 1.0f : 0.0f;
        v = fmaf(so.w, -vth, v);

        row[i] = so;   // overwrite input with spike (same thread, no hazard)
    }
    __syncthreads();

    // ---- Phase S: coalesced smem -> gmem store ----
    #pragma unroll
    for (int i = 0; i < T_VEC; ++i) {
        out[base + tid + ROWS_CTA * i] = tile[tid + ROWS_CTA * i];
    }
}

extern "C" void kernel_launch(void* const* d_in, const int* in_sizes, int n_in,
                              void* d_out, int out_size) {
    const float4* x = (const float4*)d_in[0];
    float4* out = (float4*)d_out;

    int n_rows = in_sizes[0] / T_STEPS;          // 524288
    int blocks = n_rows / ROWS_CTA;              // 4096

    size_t smem_bytes = TILE_V4 * sizeof(float4);   // 50 KB
    static bool attr_set = false;
    if (!attr_set) {
        cudaFuncSetAttribute(lif_kernel, cudaFuncAttributeMaxDynamicSharedMemorySize,
                             (int)smem_bytes);
        attr_set = true;
    }
    lif_kernel<<<blocks, ROWS_CTA, smem_bytes>>>(x, out);
}

// round 8
// speedup vs baseline: 2.8972x; 1.0585x over previous
#include <cuda_runtime.h>

// LIF neuron scan, round 7: persistent CTAs + cp.async double-buffered pipeline.
//
// Round-6 diagnosis: DRAM stuck at 58% because phase overlap across 4 CTAs/SM
// is statistical; compute+store windows (~2000 cyc, smem-bound) starve DRAM.
// Fix: deterministic overlap. Each persistent CTA double-buffers tiles with
// cp.async.cg (L1-bypass DMA): tile k+1 streams into buffer B while tile k is
// computed in place and stored from buffer A. 2x50 KB smem -> 2 CTAs/SM.

#define T_STEPS   100
#define T_VEC     (T_STEPS / 4)        // 25 float4 per row
#define ROWS_CTA  128
#define TILE_V4   (ROWS_CTA * T_VEC)   // 3200 float4 = 50 KB
#define GRID_P    296                  // ~2 persistent CTAs per SM

__device__ __forceinline__ void cp_async16(float4* smem_dst, const float4* gmem_src) {
    unsigned saddr = (unsigned)__cvta_generic_to_shared(smem_dst);
    asm volatile("cp.async.cg.shared.global [%0], [%1], 16;\n" :: "r"(saddr), "l"(gmem_src));
}
__device__ __forceinline__ void cp_commit() {
    asm volatile("cp.async.commit_group;\n");
}
template <int N>
__device__ __forceinline__ void cp_wait() {
    asm volatile("cp.async.wait_group %0;\n" :: "n"(N));
}

__global__ __launch_bounds__(ROWS_CTA, 2) void lif_kernel(const float4* __restrict__ x,
                                                          float4* __restrict__ out,
                                                          int ntiles) {
    extern __shared__ float4 smem[];              // [2 * TILE_V4]
    float4* buf0 = smem;
    float4* buf1 = smem + TILE_V4;

    const int tid    = threadIdx.x;
    const int stride = gridDim.x;

    int tile0 = blockIdx.x;
    if (tile0 >= ntiles) return;

    // Prologue: prefetch first tile into buf0.
    {
        const float4* src = x + (long long)tile0 * TILE_V4;
        #pragma unroll
        for (int i = 0; i < T_VEC; ++i)
            cp_async16(&buf0[tid + ROWS_CTA * i], &src[tid + ROWS_CTA * i]);
        cp_commit();
    }

    int pb = 0;
    for (int tile = tile0; tile < ntiles; tile += stride) {
        float4* cur = pb ? buf1 : buf0;
        float4* nxt = pb ? buf0 : buf1;

        // Prefetch next tile into the other buffer, then wait for current.
        int next = tile + stride;
        if (next < ntiles) {
            const float4* src = x + (long long)next * TILE_V4;
            #pragma unroll
            for (int i = 0; i < T_VEC; ++i)
                cp_async16(&nxt[tid + ROWS_CTA * i], &src[tid + ROWS_CTA * i]);
            cp_commit();
            cp_wait<1>();       // current tile's group has landed
        } else {
            cp_wait<0>();
        }
        __syncthreads();

        // ---- Compute: serial LIF scan of this thread's row, in place ----
        const float decay = 0.5f;
        const float vth   = 0.5f;
        float v = 0.0f;
        float4* __restrict__ row = cur + tid * T_VEC;

        #pragma unroll
        for (int i = 0; i < T_VEC; ++i) {
            float4 xi = row[i];
            float4 so;

            v = fmaf(v, decay, xi.x);
            so.x = (v > vth) ? 1.0f : 0.0f;
            v = fmaf(so.x, -vth, v);

            v = fmaf(v, decay, xi.y);
            so.y = (v > vth) ? 1.0f : 0.0f;
            v = fmaf(so.y, -vth, v);

            v = fmaf(v, decay, xi.z);
            so.z = (v > vth) ? 1.0f : 0.0f;
            v = fmaf(so.z, -vth, v);

            v = fmaf(v, decay, xi.w);
            so.w = (v > vth) ? 1.0f : 0.0f;
            v = fmaf(so.w, -vth, v);

            row[i] = so;
        }
        __syncthreads();

        // ---- Store: coalesced smem -> gmem ----
        float4* dst = out + (long long)tile * TILE_V4;
        #pragma unroll
        for (int i = 0; i < T_VEC; ++i)
            dst[tid + ROWS_CTA * i] = cur[tid + ROWS_CTA * i];

        // Protect cur: next iteration's prefetch writes into this buffer.
        __syncthreads();

        pb ^= 1;
    }
}

extern "C" void kernel_launch(void* const* d_in, const int* in_sizes, int n_in,
                              void* d_out, int out_size) {
    const float4* x = (const float4*)d_in[0];
    float4* out = (float4*)d_out;

    int n_rows = in_sizes[0] / T_STEPS;          // 524288
    int ntiles = n_rows / ROWS_CTA;              // 4096

    size_t smem_bytes = 2 * TILE_V4 * sizeof(float4);   // 100 KB
    static bool attr_set = false;
    if (!attr_set) {
        cudaFuncSetAttribute(lif_kernel, cudaFuncAttributeMaxDynamicSharedMemorySize,
                             (int)smem_bytes);
        attr_set = true;
    }
    int grid = ntiles < GRID_P ? ntiles : GRID_P;
    lif_kernel<<<grid, ROWS_CTA, smem_bytes>>>(x, out, ntiles);
}

// round 10
// speedup vs baseline: 3.2959x; 1.1376x over previous
#include <cuda_runtime.h>

// LIF neuron scan, round 9: 3-buffer ring fixes the bulk-store WAR race.
//
// Round-8 bug: with 2 buffers, a buffer's bulk store was only 1 iteration old
// when the buffer was reused as prefetch target, and bulk_wait<1> let exactly
// that store stay in flight while cp.async overwrote it (rel_err 8e-2).
// Fix: 3-buffer ring. A buffer's store is 2 iterations old at reuse, so
// wait<1> (allow the newest store to remain outstanding) is provably safe and
// keeps stores fully asynchronous.
//
// 3 x 50 KB = 150 KB smem -> 1 persistent CTA/SM (grid 148). Per tile:
// compute ~1300 cyc < memory drain ~2400 cyc, so with async loads AND stores
// the kernel binds purely on the memory system.

#define T_STEPS   100
#define T_VEC     (T_STEPS / 4)        // 25 float4 per row
#define ROWS_CTA  128
#define TILE_V4   (ROWS_CTA * T_VEC)   // 3200 float4 = 50 KB
#define TILE_BYTES (TILE_V4 * 16)
#define GRID_P    148                  // 1 persistent CTA per SM

__device__ __forceinline__ void cp_async16(float4* smem_dst, const float4* gmem_src) {
    unsigned saddr = (unsigned)__cvta_generic_to_shared(smem_dst);
    asm volatile("cp.async.cg.shared.global [%0], [%1], 16;\n" :: "r"(saddr), "l"(gmem_src));
}
__device__ __forceinline__ void cp_commit() {
    asm volatile("cp.async.commit_group;\n");
}
template <int N>
__device__ __forceinline__ void cp_wait() {
    asm volatile("cp.async.wait_group %0;\n" :: "n"(N));
}

// Bulk smem -> gmem DMA (separate group mechanism from cp.async above).
__device__ __forceinline__ void bulk_store(float4* gmem_dst, const float4* smem_src, unsigned bytes) {
    unsigned saddr = (unsigned)__cvta_generic_to_shared(smem_src);
    asm volatile("cp.async.bulk.global.shared::cta.bulk_group [%0], [%1], %2;\n"
                 :: "l"(gmem_dst), "r"(saddr), "r"(bytes) : "memory");
}
__device__ __forceinline__ void bulk_commit() {
    asm volatile("cp.async.bulk.commit_group;\n");
}
template <int N>
__device__ __forceinline__ void bulk_wait() {
    asm volatile("cp.async.bulk.wait_group %0;\n" :: "n"(N) : "memory");
}
__device__ __forceinline__ void fence_async_proxy() {
    asm volatile("fence.proxy.async.shared::cta;\n" ::: "memory");
}

__global__ __launch_bounds__(ROWS_CTA, 1) void lif_kernel(const float4* __restrict__ x,
                                                          float4* __restrict__ out,
                                                          int ntiles) {
    extern __shared__ float4 smem[];              // [3 * TILE_V4]
    float4* bA = smem;                            // ring: cur, next, spare
    float4* bB = smem + TILE_V4;
    float4* bC = smem + 2 * TILE_V4;

    const int tid    = threadIdx.x;
    const int stride = gridDim.x;

    int tile0 = blockIdx.x;
    if (tile0 >= ntiles) return;

    // Prologue: prefetch first tile into bA.
    {
        const float4* src = x + (long long)tile0 * TILE_V4;
        #pragma unroll
        for (int i = 0; i < T_VEC; ++i)
            cp_async16(&bA[tid + ROWS_CTA * i], &src[tid + ROWS_CTA * i]);
        cp_commit();
    }

    for (int tile = tile0; tile < ntiles; tile += stride) {
        float4* cur = bA;
        float4* nxt = bB;

        int next = tile + stride;
        if (next < ntiles) {
            // nxt's bulk store was issued 2 iterations ago. Outstanding stores
            // now: {iter-2 (on nxt), iter-1}. wait<1> drains iter-2, leaves
            // iter-1 in flight -> safe to overwrite nxt, store stays async.
            if (tid == 0) bulk_wait<1>();
            __syncthreads();

            const float4* src = x + (long long)next * TILE_V4;
            #pragma unroll
            for (int i = 0; i < T_VEC; ++i)
                cp_async16(&nxt[tid + ROWS_CTA * i], &src[tid + ROWS_CTA * i]);
            cp_commit();
            cp_wait<1>();       // current tile's load group has landed
        } else {
            cp_wait<0>();
        }
        __syncthreads();

        // ---- Compute: serial LIF scan of this thread's row, in place ----
        const float decay = 0.5f;
        const float vth   = 0.5f;
        float v = 0.0f;
        float4* __restrict__ row = cur + tid * T_VEC;

        #pragma unroll
        for (int i = 0; i < T_VEC; ++i) {
            float4 xi = row[i];
            float4 so;

            v = fmaf(v, decay, xi.x);
            so.x = (v > vth) ? 1.0f : 0.0f;
            v = fmaf(so.x, -vth, v);

            v = fmaf(v, decay, xi.y);
            so.y = (v > vth) ? 1.0f : 0.0f;
            v = fmaf(so.y, -vth, v);

            v = fmaf(v, decay, xi.z);
            so.z = (v > vth) ? 1.0f : 0.0f;
            v = fmaf(so.z, -vth, v);

            v = fmaf(v, decay, xi.w);
            so.w = (v > vth) ? 1.0f : 0.0f;
            v = fmaf(so.w, -vth, v);

            row[i] = so;
        }

        // Order generic smem writes before the async-proxy bulk read, then
        // fire-and-forget the 50 KB tile store.
        fence_async_proxy();
        __syncthreads();
        if (tid == 0) {
            bulk_store(out + (long long)tile * TILE_V4, cur, TILE_BYTES);
            bulk_commit();
        }

        // Rotate ring: A<-B (next tile's data), B<-C (free), C<-A (storing).
        float4* t = bA; bA = bB; bB = bC; bC = t;
    }

    // Drain outstanding bulk stores before exit.
    if (tid == 0) bulk_wait<0>();
}

extern "C" void kernel_launch(void* const* d_in, const int* in_sizes, int n_in,
                              void* d_out, int out_size) {
    const float4* x = (const float4*)d_in[0];
    float4* out = (float4*)d_out;

    int n_rows = in_sizes[0] / T_STEPS;          // 524288
    int ntiles = n_rows / ROWS_CTA;              // 4096

    size_t smem_bytes = 3 * TILE_V4 * sizeof(float4);   // 150 KB
    static bool attr_set = false;
    if (!attr_set) {
        cudaFuncSetAttribute(lif_kernel, cudaFuncAttributeMaxDynamicSharedMemorySize,
                             (int)smem_bytes);
        attr_set = true;
    }
    int grid = ntiles < GRID_P ? ntiles : GRID_P;
    lif_kernel<<<grid, ROWS_CTA, smem_bytes>>>(x, out, ntiles);
}